// round 10
// baseline (speedup 1.0000x reference)
#include <cuda_runtime.h>
#include <cuda_bf16.h>
#include <cuda_fp16.h>
#include <math.h>
#include <stdint.h>

#define NQ 4096
#define NC 1024
#define DD 513
#define DP 528            // fp32 padded dim
#define SEC 528           // gemm1 section width
#define K1 1600           // 3 sections * 528 = 1584 -> pad to 1600 (25*64)
#define NDIM2 512         // gemm2 N (space coords 1..512)
#define KSEC 4096         // gemm2 per-section K
#define NSPLIT 9          // gemm2 slices: 3 section-pairs x 3 K-thirds
#define NITER 20
#define EPS8 1e-8f
#define INVN (1.0f/4096.0f)

__device__ __forceinline__ uint32_t smem_u32(const void* p) {
    uint32_t a;
    asm("{ .reg .u64 t; cvta.to.shared.u64 t, %1; cvt.u32.u64 %0, t; }" : "=r"(a) : "l"(p));
    return a;
}

// ================= persistent buffers =================
__device__ float g_qhat  [NQ * DP];
__device__ float g_protos[NC * DP];
__device__ float g_logits[NQ * NC];
__device__ float g_rowpart[16][NQ];      // per-(colblock,wn) partial exp-sums
__device__ float g_rowinv[NQ];
__device__ float g_cm    [NC];
__device__ float g_colpart[32 * NC];
__device__ float g_m     [NC * DP];
__device__ float g_v     [NC * DP];
__device__ unsigned int g_cnt;           // colpart completion counter (self-wrapping)
__device__ int g_flag;                   // cm-ready flag (reset by adam)
__device__ __half g_q3 [(size_t)NQ * K1];                 // [qh|qh|ql] fp16
__device__ __half g_p3 [(size_t)NC * K1];                 // [ph|pl|ph] fp16
__device__ __nv_bfloat16 g_qT2[2][(size_t)NDIM2 * KSEC];  // [qh^T], [ql^T] bf16
__device__ __nv_bfloat16 g_Wrow[2][(size_t)NQ * NC];      // Wh, Wl row-major [i][j]
__device__ float g_gpart[NSPLIT * (size_t)NC * NDIM2];

__device__ __forceinline__ void split2b(float v, __nv_bfloat16& hi, __nv_bfloat16& lo) {
    hi = __float2bfloat16(v);
    lo = __float2bfloat16(v - __bfloat162float(hi));
}
__device__ __forceinline__ void split2h(float v, __half& hi, __half& lo) {
    hi = __float2half(v);
    lo = __float2half(v - __half2float(hi));
}

// ================= prep =================
__global__ void prep_p_kernel(const float* __restrict__ p) {
    int idx = blockIdx.x * blockDim.x + threadIdx.x;
    if (idx >= NC * DP) return;
    int i = idx / DP, d = idx % DP;
    float v = 0.0f;
    if (d < DD) v = p[i * DD + d];
    g_protos[idx] = v;
    g_m[idx] = 0.0f;
    g_v[idx] = 0.0f;
}
__global__ void split_p_kernel() {
    int idx = blockIdx.x * blockDim.x + threadIdx.x;
    if (idx >= NC * K1) return;
    int j = idx / K1, d = idx % K1;
    __half out = __float2half(0.0f);
    if (d < 3 * SEC) {
        int sec = d / SEC, dd = d % SEC;
        float v = g_protos[j * DP + dd];
        __half hi, lo; split2h(v, hi, lo);
        out = (sec == 1) ? lo : hi;
    }
    g_p3[(size_t)j * K1 + d] = out;
}
__global__ void prep_q_kernel(const float* __restrict__ q) {
    int idx = blockIdx.x * blockDim.x + threadIdx.x;
    if (idx >= NQ * DP) return;
    int i = idx / DP, d = idx % DP;
    float v = 0.0f;
    if (d < DD) { v = q[i * DD + d]; if (d > 0) v = -v; }
    g_qhat[idx] = v;
}
__global__ void prep_q3_kernel() {
    int idx = blockIdx.x * blockDim.x + threadIdx.x;
    if (idx >= NQ * K1) return;
    int i = idx / K1, d = idx % K1;
    __half out = __float2half(0.0f);
    if (d < 3 * SEC) {
        int sec = d / SEC, dd = d % SEC;
        float v = g_qhat[i * DP + dd];
        __half hi, lo; split2h(v, hi, lo);
        out = (sec < 2) ? hi : lo;
    }
    g_q3[(size_t)i * K1 + d] = out;
}
__global__ void prep_qT2_kernel() {
    int idx = blockIdx.x * blockDim.x + threadIdx.x;
    if (idx >= NDIM2 * NQ) return;
    int r = idx / NQ, i = idx % NQ;
    float v = g_qhat[i * DP + r + 1];
    __nv_bfloat16 hi, lo; split2b(v, hi, lo);
    g_qT2[0][(size_t)r * KSEC + i] = hi;
    g_qT2[1][(size_t)r * KSEC + i] = lo;
}

// ================= mma.sync GEMM (3-stage cp.async pipeline) =================
#define SMEM_BYTES 98304

__device__ __forceinline__ void ld_x4(uint32_t* r, uint32_t addr) {
    asm volatile("ldmatrix.sync.aligned.m8n8.x4.shared.b16 {%0,%1,%2,%3}, [%4];"
        : "=r"(r[0]), "=r"(r[1]), "=r"(r[2]), "=r"(r[3]) : "r"(addr));
}
__device__ __forceinline__ void ld_x4_trans(uint32_t* r, uint32_t addr) {
    asm volatile("ldmatrix.sync.aligned.m8n8.x4.trans.shared.b16 {%0,%1,%2,%3}, [%4];"
        : "=r"(r[0]), "=r"(r[1]), "=r"(r[2]), "=r"(r[3]) : "r"(addr));
}
__device__ __forceinline__ void mma_bf16(float* d, const uint32_t* a, const uint32_t* b) {
    asm volatile("mma.sync.aligned.m16n8k16.row.col.f32.bf16.bf16.f32 "
        "{%0,%1,%2,%3}, {%4,%5,%6,%7}, {%8,%9}, {%0,%1,%2,%3};"
        : "+f"(d[0]), "+f"(d[1]), "+f"(d[2]), "+f"(d[3])
        : "r"(a[0]), "r"(a[1]), "r"(a[2]), "r"(a[3]), "r"(b[0]), "r"(b[1]));
}
__device__ __forceinline__ void mma_fp16(float* d, const uint32_t* a, const uint32_t* b) {
    asm volatile("mma.sync.aligned.m16n8k16.row.col.f32.f16.f16.f32 "
        "{%0,%1,%2,%3}, {%4,%5,%6,%7}, {%8,%9}, {%0,%1,%2,%3};"
        : "+f"(d[0]), "+f"(d[1]), "+f"(d[2]), "+f"(d[3])
        : "r"(a[0]), "r"(a[1]), "r"(a[2]), "r"(a[3]), "r"(b[0]), "r"(b[1]));
}

// MODE1 stage: A,B both K-major 128 rows x 128B
__device__ __forceinline__ void load_stage1(uint32_t sA, const char* Ab, const char* Bb,
                                            size_t kbytes, size_t gk, int tid) {
    uint32_t sB = sA + 16384;
#pragma unroll
    for (int t = 0; t < 4; t++) {
        int idx = tid + 256 * t;
        int r = idx >> 3, c = idx & 7;
        uint32_t sw = (uint32_t)(r * 128 + ((c ^ (r & 7)) << 4));
        const char* g = Ab + (size_t)r * kbytes + gk + c * 16;
        asm volatile("cp.async.cg.shared.global [%0], [%1], 16;" :: "r"(sA + sw), "l"(g));
    }
#pragma unroll
    for (int t = 0; t < 4; t++) {
        int idx = tid + 256 * t;
        int r = idx >> 3, c = idx & 7;
        uint32_t sw = (uint32_t)(r * 128 + ((c ^ (r & 7)) << 4));
        const char* g = Bb + (size_t)r * kbytes + gk + c * 16;
        asm volatile("cp.async.cg.shared.global [%0], [%1], 16;" :: "r"(sB + sw), "l"(g));
    }
    asm volatile("cp.async.commit_group;" ::: "memory");
}

// MODE2 stage: A = W row-major tile (64 k-rows x 256B), B = qT2 K-major (128 rows x 128B)
__device__ __forceinline__ void load_stage2(uint32_t sA, const char* AbW, const char* Bb,
                                            int krow0, int tid) {
    uint32_t sB = sA + 16384;
#pragma unroll
    for (int t = 0; t < 4; t++) {
        int idx = tid + 256 * t;
        int row = idx >> 4, col = idx & 15;
        uint32_t scol = (uint32_t)(col ^ (row & 7));
        const char* g = AbW + (size_t)(krow0 + row) * (NC * 2) + col * 16;
        asm volatile("cp.async.cg.shared.global [%0], [%1], 16;"
            :: "r"(sA + row * 256 + scol * 16), "l"(g));
    }
#pragma unroll
    for (int t = 0; t < 4; t++) {
        int idx = tid + 256 * t;
        int r = idx >> 3, c = idx & 7;
        uint32_t sw = (uint32_t)(r * 128 + ((c ^ (r & 7)) << 4));
        const char* g = Bb + (size_t)r * (KSEC * 2) + (size_t)krow0 * 2 + c * 16;
        asm volatile("cp.async.cg.shared.global [%0], [%1], 16;" :: "r"(sB + sw), "l"(g));
    }
    asm volatile("cp.async.commit_group;" ::: "memory");
}

template <int MODE>
__global__ __launch_bounds__(256, 2) void mma_gemm() {
    extern __shared__ char smem[];
    const uint32_t sb = smem_u32(smem);
    const int tid = threadIdx.x;
    const int warp = tid >> 5, lane = tid & 31;
    const int wm = warp & 3, wn = warp >> 2;

    const int m0 = blockIdx.y * 128;
    const int n0 = blockIdx.x * 128;
    const char* Abase;
    const char* Bbase;
    int nch, krowbase = 0;
    if (MODE == 1) {
        Abase = (const char*)g_q3 + (size_t)m0 * K1 * 2;
        Bbase = (const char*)g_p3 + (size_t)n0 * K1 * 2;
        nch = K1 / 64;
    } else {
        int z = blockIdx.z;
        int s = z / 3, h = z % 3;
        int ai = (s == 2) ? 1 : 0;
        int bi = (s == 1) ? 1 : 0;
        Abase = (const char*)&g_Wrow[ai][0] + (size_t)m0 * 2;      // + krow*NC*2
        Bbase = (const char*)&g_qT2[bi][0] + (size_t)n0 * KSEC * 2;
        nch = (h < 2) ? 22 : 20;
        krowbase = h * 22 * 64;
    }

    if (MODE == 1) {
        load_stage1(sb, Abase, Bbase, K1 * 2, 0, tid);
        load_stage1(sb + 32768, Abase, Bbase, K1 * 2, 128, tid);
    } else {
        load_stage2(sb, Abase, Bbase, krowbase, tid);
        load_stage2(sb + 32768, Abase, Bbase, krowbase + 64, tid);
    }
    asm volatile("cp.async.wait_group 1;" ::: "memory");
    __syncthreads();

    float acc[2][8][4];
#pragma unroll
    for (int mt = 0; mt < 2; mt++)
#pragma unroll
        for (int nt = 0; nt < 8; nt++)
#pragma unroll
            for (int e = 0; e < 4; e++) acc[mt][nt][e] = 0.0f;

    for (int ch = 0; ch < nch; ch++) {
        const uint32_t sA = sb + (uint32_t)(ch % 3) * 32768;
        const uint32_t sB = sA + 16384;

#pragma unroll
        for (int kk = 0; kk < 4; kk++) {
            uint32_t a[2][4], b[8][2];
#pragma unroll
            for (int mt = 0; mt < 2; mt++) {
                if (MODE == 1) {
                    int r = wm * 32 + mt * 16 + (lane & 15);
                    int c = ((lane >> 4) + 2 * kk) ^ (r & 7);
                    ld_x4(a[mt], sA + r * 128 + c * 16);
                } else {
                    int krow = 16 * kk + (lane & 7) + ((lane >> 4) << 3);
                    int mcol = wm * 4 + mt * 2 + ((lane >> 3) & 1);
                    int scol = mcol ^ (krow & 7);
                    ld_x4_trans(a[mt], sA + krow * 256 + scol * 16);
                }
            }
#pragma unroll
            for (int np = 0; np < 4; np++) {
                int r = wn * 64 + np * 16 + (lane & 7) + ((lane >> 4) << 3);
                int c = (((lane >> 3) & 1) + 2 * kk) ^ (r & 7);
                uint32_t tmp[4];
                ld_x4(tmp, sB + r * 128 + c * 16);
                b[2 * np][0] = tmp[0]; b[2 * np][1] = tmp[1];
                b[2 * np + 1][0] = tmp[2]; b[2 * np + 1][1] = tmp[3];
            }
#pragma unroll
            for (int mt = 0; mt < 2; mt++)
#pragma unroll
                for (int nt = 0; nt < 8; nt++) {
                    if (MODE == 1) mma_fp16(acc[mt][nt], a[mt], b[nt]);
                    else           mma_bf16(acc[mt][nt], a[mt], b[nt]);
                }
        }

        if (ch + 2 < nch) {
            if (MODE == 1)
                load_stage1(sb + (uint32_t)((ch + 2) % 3) * 32768, Abase, Bbase,
                            K1 * 2, (size_t)(ch + 2) * 128, tid);
            else
                load_stage2(sb + (uint32_t)((ch + 2) % 3) * 32768, Abase, Bbase,
                            krowbase + (ch + 2) * 64, tid);
            asm volatile("cp.async.wait_group 1;" ::: "memory");
        } else {
            asm volatile("cp.async.wait_group 0;" ::: "memory");
        }
        __syncthreads();
    }

    // ---------------- epilogue ----------------
    if (MODE == 1) {
        const float CL = 1.0f + 1e-7f;
        float rowE[2][2] = {{0.0f, 0.0f}, {0.0f, 0.0f}};
#pragma unroll
        for (int mt = 0; mt < 2; mt++) {
#pragma unroll
            for (int nt = 0; nt < 8; nt++) {
                int col = n0 + wn * 64 + nt * 8 + (lane & 3) * 2;
#pragma unroll
                for (int h = 0; h < 2; h++) {
                    int row = m0 + wm * 32 + mt * 16 + (lane >> 2) + 8 * h;
                    float v0 = acc[mt][nt][2 * h + 0];
                    float v1 = acc[mt][nt][2 * h + 1];
                    float2 lg;
                    {
                        float z = fmaxf(v0, CL);
                        float w = fmaf(z, z, -1.0f);
                        float aa = __logf(fmaf(w, rsqrtf(w), z));
                        lg.x = -aa * aa;
                    }
                    {
                        float z = fmaxf(v1, CL);
                        float w = fmaf(z, z, -1.0f);
                        float aa = __logf(fmaf(w, rsqrtf(w), z));
                        lg.y = -aa * aa;
                    }
                    *(float2*)&g_logits[(size_t)row * NC + col] = lg;
                    rowE[mt][h] += __expf(lg.x) + __expf(lg.y);
                }
            }
        }
#pragma unroll
        for (int mt = 0; mt < 2; mt++)
#pragma unroll
            for (int h = 0; h < 2; h++) {
                float r = rowE[mt][h];
                r += __shfl_xor_sync(0xFFFFFFFFu, r, 1);
                r += __shfl_xor_sync(0xFFFFFFFFu, r, 2);
                if ((lane & 3) == 0) {
                    int row = m0 + wm * 32 + mt * 16 + (lane >> 2) + 8 * h;
                    g_rowpart[blockIdx.x * 2 + wn][row] = r;
                }
            }
    } else {
#pragma unroll
        for (int mt = 0; mt < 2; mt++) {
#pragma unroll
            for (int nt = 0; nt < 8; nt++) {
                int col = n0 + wn * 64 + nt * 8 + (lane & 3) * 2;
#pragma unroll
                for (int h = 0; h < 2; h++) {
                    int row = m0 + wm * 32 + mt * 16 + (lane >> 2) + 8 * h;
                    float* out = g_gpart + (size_t)blockIdx.z * NC * NDIM2;
                    float2 gv;
                    gv.x = acc[mt][nt][2 * h + 0];
                    gv.y = acc[mt][nt][2 * h + 1];
                    *(float2*)&out[(size_t)row * NDIM2 + col] = gv;
                }
            }
        }
    }
}

// ================= fused mid kernel: colpart + colreduce + rowdot + W =================
// grid 4096, block 256.
// Blocks 0..127: column partial sums (P = exp(l)*rowinv); last arrival reduces -> cm,
// sets g_flag. All blocks then spin on g_flag and run the rowdot+W body for row=blockIdx.x.
__global__ __launch_bounds__(256) void mid_kernel() {
    __shared__ float scm[NC];
    __shared__ float red[256];
    __shared__ float srinv[128];
    __shared__ int slast;
    const int bid = blockIdx.x;
    const int t = threadIdx.x;

    if (bid < 128) {
        // ---- colpart phase: jblk = bid&3 (256 cols), iblk = bid>>2 (128 rows) ----
        const int jblk = bid & 3;
        const int i0 = (bid >> 2) * 128;
        if (t < 128) {
            float s = 0.0f;
#pragma unroll
            for (int r = 0; r < 16; r++) s += g_rowpart[r][i0 + t];
            float inv = 1.0f / s;
            srinv[t] = inv;
            if (jblk == 0) g_rowinv[i0 + t] = inv;
        }
        __syncthreads();
        const int j = jblk * 256 + t;
        float s = 0.0f;
        for (int i = 0; i < 128; i++)
            s += __expf(g_logits[(size_t)(i0 + i) * NC + j]) * srinv[i];
        g_colpart[(bid >> 2) * NC + j] = s;

        // ---- completion counter; last CTA reduces -> cm ----
        __threadfence();
        __syncthreads();
        if (t == 0) {
            unsigned int old = atomicInc(&g_cnt, 127u);
            slast = (old == 127u) ? 1 : 0;
        }
        __syncthreads();
        if (slast) {
            __threadfence();
#pragma unroll
            for (int e = 0; e < 4; e++) {
                int jj = t + 256 * e;
                float cs = 0.0f;
#pragma unroll
                for (int r = 0; r < 32; r++) cs += g_colpart[r * NC + jj];
                float pm = cs * INVN;
                g_cm[jj] = __logf(pm + EPS8) + pm / (pm + EPS8);
            }
            __threadfence();
            __syncthreads();
            if (t == 0) atomicExch(&g_flag, 1);
        }
    }

    // ---- wait for cm ----
    if (t == 0) {
        while (atomicAdd(&g_flag, 0) == 0) { }
    }
    __syncthreads();
    __threadfence();

    // ---- rowdot + W phase for row = bid ----
    const int i = bid;
    const size_t base = (size_t)i * NC;
#pragma unroll
    for (int e = 0; e < 4; e++) scm[t + 256 * e] = g_cm[t + 256 * e];
    __syncthreads();

    float l[4], ex[4];
    float acc = 0.0f;
#pragma unroll
    for (int e = 0; e < 4; e++) {
        int j = t + 256 * e;
        l[e] = g_logits[base + j];
        ex[e] = __expf(l[e]);
        acc += ex[e] * (scm[j] - l[e]);
    }
    red[t] = acc; __syncthreads();
    for (int s = 128; s > 0; s >>= 1) { if (t < s) red[t] += red[t + s]; __syncthreads(); }
    const float rinv = g_rowinv[i];
    const float A = -red[0] * rinv * INVN;

#pragma unroll
    for (int e = 0; e < 4; e++) {
        int j = t + 256 * e;
        float a = sqrtf(-l[e]);
        float fv;
        if (a < 1e-3f) fv = -2.0f;
        else {
            float sh = 0.5f * (__expf(a) - __expf(-a));
            fv = -2.0f * a / sh;
        }
        float pv = ex[e] * rinv;
        float w = pv * (fmaf(scm[j] - l[e], INVN, A)) * fv;
        __nv_bfloat16 hi, lo; split2b(w, hi, lo);
        g_Wrow[0][base + j] = hi;
        g_Wrow[1][base + j] = lo;
    }
}

// ================= AdamW + reproject + emit p3 fp16 split + flag reset =================
__global__ __launch_bounds__(256) void adam_kernel(float corr1, float corr2) {
    __shared__ float red[256];
    const int j = blockIdx.x;
    const int t = threadIdx.x;
    const size_t p3base = (size_t)j * K1;

    if (j == 0 && t == 0) g_flag = 0;   // re-arm mid_kernel handshake for next iter

    float ss = 0.0f;
#pragma unroll
    for (int e = 0; e < 2; e++) {
        int c = t + 256 * e;
        int d = c + 1;
        int idx = j * DP + d;
        float g = 0.0f;
#pragma unroll
        for (int z = 0; z < NSPLIT; z++)
            g += g_gpart[(size_t)z * NC * NDIM2 + (size_t)j * NDIM2 + c];
        float m = 0.9f * g_m[idx] + 0.1f * g;
        float v = 0.999f * g_v[idx] + 0.001f * (g * g);
        g_m[idx] = m; g_v[idx] = v;
        float mh = m * corr1;
        float vh = v * corr2;
        float xx = g_protos[idx] * 0.999f - 0.1f * mh / (sqrtf(vh) + EPS8);
        g_protos[idx] = xx;
        __half hi, lo; split2h(xx, hi, lo);
        g_p3[p3base + d] = hi;
        g_p3[p3base + SEC + d] = lo;
        g_p3[p3base + 2 * SEC + d] = hi;
        ss += xx * xx;
    }
    red[t] = ss; __syncthreads();
    for (int sft = 128; sft > 0; sft >>= 1) { if (t < sft) red[t] += red[t + sft]; __syncthreads(); }
    if (t == 0) {
        float tm = sqrtf(1.0f + red[0]);
        g_protos[j * DP] = tm;
        __half hi, lo; split2h(tm, hi, lo);
        g_p3[p3base] = hi;
        g_p3[p3base + SEC] = lo;
        g_p3[p3base + 2 * SEC] = hi;
    }
}

__global__ void pack_kernel(float* __restrict__ out) {
    int idx = blockIdx.x * blockDim.x + threadIdx.x;
    if (idx >= NC * DD) return;
    int i = idx / DD, d = idx % DD;
    out[idx] = g_protos[i * DP + d];
}

// ================= launch =================
extern "C" void kernel_launch(void* const* d_in, const int* in_sizes, int n_in,
                              void* d_out, int out_size) {
    const float* protos_in = (const float*)d_in[0];
    const float* query_in  = (const float*)d_in[1];
    (void)in_sizes; (void)n_in; (void)out_size;

    cudaFuncSetAttribute(mma_gemm<1>, cudaFuncAttributeMaxDynamicSharedMemorySize, SMEM_BYTES);
    cudaFuncSetAttribute(mma_gemm<2>, cudaFuncAttributeMaxDynamicSharedMemorySize, SMEM_BYTES);

    // ordered so the 6th launch (ncu -s 5 -c 1) is mma_gemm<1>
    prep_p_kernel<<<(NC * DP + 255) / 256, 256>>>(protos_in);
    split_p_kernel<<<(NC * K1 + 255) / 256, 256>>>();
    prep_q_kernel<<<(NQ * DP + 255) / 256, 256>>>(query_in);
    prep_q3_kernel<<<(NQ * K1 + 255) / 256, 256>>>();
    prep_qT2_kernel<<<(NDIM2 * NQ + 255) / 256, 256>>>();

    for (int t = 1; t <= NITER; t++) {
        mma_gemm<1><<<dim3(NC / 128, NQ / 128), 256, SMEM_BYTES>>>();
        mid_kernel<<<NQ, 256>>>();
        mma_gemm<2><<<dim3(NDIM2 / 128, NC / 128, NSPLIT), 256, SMEM_BYTES>>>();
        double c1 = 1.0 / (1.0 - pow(0.9,   (double)t));
        double c2 = 1.0 / (1.0 - pow(0.999, (double)t));
        adam_kernel<<<NC, 256>>>((float)c1, (float)c2);
    }
    pack_kernel<<<(NC * DD + 255) / 256, 256>>>((float*)d_out);
}

// round 11
// speedup vs baseline: 1.0849x; 1.0849x over previous
#include <cuda_runtime.h>
#include <cuda_bf16.h>
#include <cuda_fp16.h>
#include <math.h>
#include <stdint.h>

#define NQ 4096
#define NC 1024
#define DD 513
#define DP 528            // fp32 padded dim
#define SEC 528           // gemm1 section width
#define K1 1600           // 3 sections * 528 = 1584 -> pad to 1600 (25*64)
#define NDIM2 512         // gemm2 N (space coords 1..512)
#define KSEC 4096         // gemm2 per-section K
#define NSPLIT 9          // gemm2 slices: 3 section-pairs x 3 K-thirds
#define NITER 20
#define EPS8 1e-8f
#define INVN (1.0f/4096.0f)

__device__ __forceinline__ uint32_t smem_u32(const void* p) {
    uint32_t a;
    asm("{ .reg .u64 t; cvta.to.shared.u64 t, %1; cvt.u32.u64 %0, t; }" : "=r"(a) : "l"(p));
    return a;
}

// ================= persistent buffers =================
__device__ float g_qhat  [NQ * DP];
__device__ float g_protos[NC * DP];
__device__ float g_logits[NQ * NC];
__device__ float g_rowpart[16][NQ];      // per-(colblock,wn) partial exp-sums
__device__ float g_rowinv[NQ];
__device__ float g_cm    [NC];
__device__ float g_colpart[32 * NC];
__device__ float g_m     [NC * DP];
__device__ float g_v     [NC * DP];
__device__ unsigned int g_cnt;           // colpart completion counter (self-wrapping)
__device__ __half g_q3 [(size_t)NQ * K1];                 // [qh|qh|ql] fp16
__device__ __half g_p3 [(size_t)NC * K1];                 // [ph|pl|ph] fp16
__device__ __nv_bfloat16 g_qT2[2][(size_t)NDIM2 * KSEC];  // [qh^T], [ql^T] bf16
__device__ __nv_bfloat16 g_Wrow[2][(size_t)NQ * NC];      // Wh, Wl row-major [i][j]
__device__ float g_gpart[NSPLIT * (size_t)NC * NDIM2];

__device__ __forceinline__ void split2b(float v, __nv_bfloat16& hi, __nv_bfloat16& lo) {
    hi = __float2bfloat16(v);
    lo = __float2bfloat16(v - __bfloat162float(hi));
}
__device__ __forceinline__ void split2h(float v, __half& hi, __half& lo) {
    hi = __float2half(v);
    lo = __float2half(v - __half2float(hi));
}

// ================= prep =================
__global__ void prep_q_kernel(const float* __restrict__ q) {
    int idx = blockIdx.x * blockDim.x + threadIdx.x;
    if (idx >= NQ * DP) return;
    int i = idx / DP, d = idx % DP;
    float v = 0.0f;
    if (d < DD) { v = q[i * DD + d]; if (d > 0) v = -v; }
    g_qhat[idx] = v;
}
__global__ void prep_q3_kernel() {
    int idx = blockIdx.x * blockDim.x + threadIdx.x;
    if (idx >= NQ * K1) return;
    int i = idx / K1, d = idx % K1;
    __half out = __float2half(0.0f);
    if (d < 3 * SEC) {
        int sec = d / SEC, dd = d % SEC;
        float v = g_qhat[i * DP + dd];
        __half hi, lo; split2h(v, hi, lo);
        out = (sec < 2) ? hi : lo;
    }
    g_q3[(size_t)i * K1 + d] = out;
}
__global__ void prep_qT2_kernel() {
    int idx = blockIdx.x * blockDim.x + threadIdx.x;
    if (idx >= NDIM2 * NQ) return;
    int r = idx / NQ, i = idx % NQ;
    float v = g_qhat[i * DP + r + 1];
    __nv_bfloat16 hi, lo; split2b(v, hi, lo);
    g_qT2[0][(size_t)r * KSEC + i] = hi;
    g_qT2[1][(size_t)r * KSEC + i] = lo;
}
__global__ void prep_p_kernel(const float* __restrict__ p) {
    int idx = blockIdx.x * blockDim.x + threadIdx.x;
    if (idx >= NC * DP) return;
    int i = idx / DP, d = idx % DP;
    float v = 0.0f;
    if (d < DD) v = p[i * DD + d];
    g_protos[idx] = v;
    g_m[idx] = 0.0f;
    g_v[idx] = 0.0f;
}
__global__ void split_p_kernel() {
    int idx = blockIdx.x * blockDim.x + threadIdx.x;
    if (idx >= NC * K1) return;
    int j = idx / K1, d = idx % K1;
    __half out = __float2half(0.0f);
    if (d < 3 * SEC) {
        int sec = d / SEC, dd = d % SEC;
        float v = g_protos[j * DP + dd];
        __half hi, lo; split2h(v, hi, lo);
        out = (sec == 1) ? lo : hi;
    }
    g_p3[(size_t)j * K1 + d] = out;
}

// ================= mma.sync GEMM (3-stage cp.async pipeline) =================
#define SMEM_BYTES 98304

__device__ __forceinline__ void ld_x4(uint32_t* r, uint32_t addr) {
    asm volatile("ldmatrix.sync.aligned.m8n8.x4.shared.b16 {%0,%1,%2,%3}, [%4];"
        : "=r"(r[0]), "=r"(r[1]), "=r"(r[2]), "=r"(r[3]) : "r"(addr));
}
__device__ __forceinline__ void ld_x4_trans(uint32_t* r, uint32_t addr) {
    asm volatile("ldmatrix.sync.aligned.m8n8.x4.trans.shared.b16 {%0,%1,%2,%3}, [%4];"
        : "=r"(r[0]), "=r"(r[1]), "=r"(r[2]), "=r"(r[3]) : "r"(addr));
}
__device__ __forceinline__ void mma_bf16(float* d, const uint32_t* a, const uint32_t* b) {
    asm volatile("mma.sync.aligned.m16n8k16.row.col.f32.bf16.bf16.f32 "
        "{%0,%1,%2,%3}, {%4,%5,%6,%7}, {%8,%9}, {%0,%1,%2,%3};"
        : "+f"(d[0]), "+f"(d[1]), "+f"(d[2]), "+f"(d[3])
        : "r"(a[0]), "r"(a[1]), "r"(a[2]), "r"(a[3]), "r"(b[0]), "r"(b[1]));
}
__device__ __forceinline__ void mma_fp16(float* d, const uint32_t* a, const uint32_t* b) {
    asm volatile("mma.sync.aligned.m16n8k16.row.col.f32.f16.f16.f32 "
        "{%0,%1,%2,%3}, {%4,%5,%6,%7}, {%8,%9}, {%0,%1,%2,%3};"
        : "+f"(d[0]), "+f"(d[1]), "+f"(d[2]), "+f"(d[3])
        : "r"(a[0]), "r"(a[1]), "r"(a[2]), "r"(a[3]), "r"(b[0]), "r"(b[1]));
}

// MODE1 stage: A,B both K-major 128 rows x 128B
__device__ __forceinline__ void load_stage1(uint32_t sA, const char* Ab, const char* Bb,
                                            size_t kbytes, size_t gk, int tid) {
    uint32_t sB = sA + 16384;
#pragma unroll
    for (int t = 0; t < 4; t++) {
        int idx = tid + 256 * t;
        int r = idx >> 3, c = idx & 7;
        uint32_t sw = (uint32_t)(r * 128 + ((c ^ (r & 7)) << 4));
        const char* g = Ab + (size_t)r * kbytes + gk + c * 16;
        asm volatile("cp.async.cg.shared.global [%0], [%1], 16;" :: "r"(sA + sw), "l"(g));
    }
#pragma unroll
    for (int t = 0; t < 4; t++) {
        int idx = tid + 256 * t;
        int r = idx >> 3, c = idx & 7;
        uint32_t sw = (uint32_t)(r * 128 + ((c ^ (r & 7)) << 4));
        const char* g = Bb + (size_t)r * kbytes + gk + c * 16;
        asm volatile("cp.async.cg.shared.global [%0], [%1], 16;" :: "r"(sB + sw), "l"(g));
    }
    asm volatile("cp.async.commit_group;" ::: "memory");
}

// MODE2 stage: A = W row-major tile (64 k-rows x 256B), B = qT2 K-major (128 rows x 128B)
__device__ __forceinline__ void load_stage2(uint32_t sA, const char* AbW, const char* Bb,
                                            int krow0, int tid) {
    uint32_t sB = sA + 16384;
#pragma unroll
    for (int t = 0; t < 4; t++) {
        int idx = tid + 256 * t;
        int row = idx >> 4, col = idx & 15;
        uint32_t scol = (uint32_t)(col ^ (row & 7));
        const char* g = AbW + (size_t)(krow0 + row) * (NC * 2) + col * 16;
        asm volatile("cp.async.cg.shared.global [%0], [%1], 16;"
            :: "r"(sA + row * 256 + scol * 16), "l"(g));
    }
#pragma unroll
    for (int t = 0; t < 4; t++) {
        int idx = tid + 256 * t;
        int r = idx >> 3, c = idx & 7;
        uint32_t sw = (uint32_t)(r * 128 + ((c ^ (r & 7)) << 4));
        const char* g = Bb + (size_t)r * (KSEC * 2) + (size_t)krow0 * 2 + c * 16;
        asm volatile("cp.async.cg.shared.global [%0], [%1], 16;" :: "r"(sB + sw), "l"(g));
    }
    asm volatile("cp.async.commit_group;" ::: "memory");
}

template <int MODE>
__global__ __launch_bounds__(256, 2) void mma_gemm() {
    extern __shared__ char smem[];
    const uint32_t sb = smem_u32(smem);
    const int tid = threadIdx.x;
    const int warp = tid >> 5, lane = tid & 31;
    const int wm = warp & 3, wn = warp >> 2;

    const int m0 = blockIdx.y * 128;
    const int n0 = blockIdx.x * 128;
    const char* Abase;
    const char* Bbase;
    int nch, krowbase = 0;
    if (MODE == 1) {
        Abase = (const char*)g_q3 + (size_t)m0 * K1 * 2;
        Bbase = (const char*)g_p3 + (size_t)n0 * K1 * 2;
        nch = K1 / 64;
    } else {
        int z = blockIdx.z;
        int s = z / 3, h = z % 3;
        int ai = (s == 2) ? 1 : 0;
        int bi = (s == 1) ? 1 : 0;
        Abase = (const char*)&g_Wrow[ai][0] + (size_t)m0 * 2;      // + krow*NC*2
        Bbase = (const char*)&g_qT2[bi][0] + (size_t)n0 * KSEC * 2;
        nch = (h < 2) ? 22 : 20;
        krowbase = h * 22 * 64;
    }

    if (MODE == 1) {
        load_stage1(sb, Abase, Bbase, K1 * 2, 0, tid);
        load_stage1(sb + 32768, Abase, Bbase, K1 * 2, 128, tid);
    } else {
        load_stage2(sb, Abase, Bbase, krowbase, tid);
        load_stage2(sb + 32768, Abase, Bbase, krowbase + 64, tid);
    }
    asm volatile("cp.async.wait_group 1;" ::: "memory");
    __syncthreads();

    float acc[2][8][4];
#pragma unroll
    for (int mt = 0; mt < 2; mt++)
#pragma unroll
        for (int nt = 0; nt < 8; nt++)
#pragma unroll
            for (int e = 0; e < 4; e++) acc[mt][nt][e] = 0.0f;

    for (int ch = 0; ch < nch; ch++) {
        const uint32_t sA = sb + (uint32_t)(ch % 3) * 32768;
        const uint32_t sB = sA + 16384;

#pragma unroll
        for (int kk = 0; kk < 4; kk++) {
            uint32_t a[2][4], b[8][2];
#pragma unroll
            for (int mt = 0; mt < 2; mt++) {
                if (MODE == 1) {
                    int r = wm * 32 + mt * 16 + (lane & 15);
                    int c = ((lane >> 4) + 2 * kk) ^ (r & 7);
                    ld_x4(a[mt], sA + r * 128 + c * 16);
                } else {
                    int krow = 16 * kk + (lane & 7) + ((lane >> 4) << 3);
                    int mcol = wm * 4 + mt * 2 + ((lane >> 3) & 1);
                    int scol = mcol ^ (krow & 7);
                    ld_x4_trans(a[mt], sA + krow * 256 + scol * 16);
                }
            }
#pragma unroll
            for (int np = 0; np < 4; np++) {
                int r = wn * 64 + np * 16 + (lane & 7) + ((lane >> 4) << 3);
                int c = (((lane >> 3) & 1) + 2 * kk) ^ (r & 7);
                uint32_t tmp[4];
                ld_x4(tmp, sB + r * 128 + c * 16);
                b[2 * np][0] = tmp[0]; b[2 * np][1] = tmp[1];
                b[2 * np + 1][0] = tmp[2]; b[2 * np + 1][1] = tmp[3];
            }
#pragma unroll
            for (int mt = 0; mt < 2; mt++)
#pragma unroll
                for (int nt = 0; nt < 8; nt++) {
                    if (MODE == 1) mma_fp16(acc[mt][nt], a[mt], b[nt]);
                    else           mma_bf16(acc[mt][nt], a[mt], b[nt]);
                }
        }

        if (ch + 2 < nch) {
            if (MODE == 1)
                load_stage1(sb + (uint32_t)((ch + 2) % 3) * 32768, Abase, Bbase,
                            K1 * 2, (size_t)(ch + 2) * 128, tid);
            else
                load_stage2(sb + (uint32_t)((ch + 2) % 3) * 32768, Abase, Bbase,
                            krowbase + (ch + 2) * 64, tid);
            asm volatile("cp.async.wait_group 1;" ::: "memory");
        } else {
            asm volatile("cp.async.wait_group 0;" ::: "memory");
        }
        __syncthreads();
    }

    // ---------------- epilogue ----------------
    if (MODE == 1) {
        const float CL = 1.0f + 1e-7f;
        float rowE[2][2] = {{0.0f, 0.0f}, {0.0f, 0.0f}};
#pragma unroll
        for (int mt = 0; mt < 2; mt++) {
#pragma unroll
            for (int nt = 0; nt < 8; nt++) {
                int col = n0 + wn * 64 + nt * 8 + (lane & 3) * 2;
#pragma unroll
                for (int h = 0; h < 2; h++) {
                    int row = m0 + wm * 32 + mt * 16 + (lane >> 2) + 8 * h;
                    float v0 = acc[mt][nt][2 * h + 0];
                    float v1 = acc[mt][nt][2 * h + 1];
                    float2 lg;
                    {
                        float z = fmaxf(v0, CL);
                        float w = fmaf(z, z, -1.0f);
                        float aa = __logf(fmaf(w, rsqrtf(w), z));
                        lg.x = -aa * aa;
                    }
                    {
                        float z = fmaxf(v1, CL);
                        float w = fmaf(z, z, -1.0f);
                        float aa = __logf(fmaf(w, rsqrtf(w), z));
                        lg.y = -aa * aa;
                    }
                    *(float2*)&g_logits[(size_t)row * NC + col] = lg;
                    rowE[mt][h] += __expf(lg.x) + __expf(lg.y);
                }
            }
        }
#pragma unroll
        for (int mt = 0; mt < 2; mt++)
#pragma unroll
            for (int h = 0; h < 2; h++) {
                float r = rowE[mt][h];
                r += __shfl_xor_sync(0xFFFFFFFFu, r, 1);
                r += __shfl_xor_sync(0xFFFFFFFFu, r, 2);
                if ((lane & 3) == 0) {
                    int row = m0 + wm * 32 + mt * 16 + (lane >> 2) + 8 * h;
                    g_rowpart[blockIdx.x * 2 + wn][row] = r;
                }
            }
    } else {
#pragma unroll
        for (int mt = 0; mt < 2; mt++) {
#pragma unroll
            for (int nt = 0; nt < 8; nt++) {
                int col = n0 + wn * 64 + nt * 8 + (lane & 3) * 2;
#pragma unroll
                for (int h = 0; h < 2; h++) {
                    int row = m0 + wm * 32 + mt * 16 + (lane >> 2) + 8 * h;
                    float* out = g_gpart + (size_t)blockIdx.z * NC * NDIM2;
                    float2 gv;
                    gv.x = acc[mt][nt][2 * h + 0];
                    gv.y = acc[mt][nt][2 * h + 1];
                    *(float2*)&out[(size_t)row * NDIM2 + col] = gv;
                }
            }
        }
    }
}

// ================= elementwise chain =================
// colpart (rowinv fused) + last-CTA colreduce. 128 CTAs; no CTA ever waits.
__global__ __launch_bounds__(256) void colpart_kernel() {
    __shared__ float srinv[128];
    __shared__ int slast;
    const int t = threadIdx.x;
    const int i0 = blockIdx.y * 128;
    if (t < 128) {
        float s = 0.0f;
#pragma unroll
        for (int r = 0; r < 16; r++) s += g_rowpart[r][i0 + t];
        float inv = 1.0f / s;
        srinv[t] = inv;
        if (blockIdx.x == 0) g_rowinv[i0 + t] = inv;
    }
    __syncthreads();
    const int j = blockIdx.x * 256 + t;
    float s = 0.0f;
    for (int i = 0; i < 128; i++)
        s += __expf(g_logits[(size_t)(i0 + i) * NC + j]) * srinv[i];
    g_colpart[blockIdx.y * NC + j] = s;

    // last-arriving CTA performs the column reduce -> g_cm (others exit immediately)
    __threadfence();
    __syncthreads();
    if (t == 0) {
        unsigned int old = atomicInc(&g_cnt, 127u);
        slast = (old == 127u) ? 1 : 0;
    }
    __syncthreads();
    if (slast) {
        __threadfence();
#pragma unroll
        for (int e = 0; e < 4; e++) {
            int jj = t + 256 * e;
            float cs = 0.0f;
#pragma unroll
            for (int r = 0; r < 32; r++) cs += g_colpart[r * NC + jj];
            float pm = cs * INVN;
            g_cm[jj] = __logf(pm + EPS8) + pm / (pm + EPS8);
        }
    }
}

// fused rowdot + W: A_i then W_ij = P*((cm_j-l)*invN + A_i)*factor, row-major bf16 split
__global__ __launch_bounds__(256) void rowdot_w_kernel() {
    __shared__ float scm[NC];
    __shared__ float red[256];
    const int i = blockIdx.x;
    const int t = threadIdx.x;
    const size_t base = (size_t)i * NC;
#pragma unroll
    for (int e = 0; e < 4; e++) scm[t + 256 * e] = g_cm[t + 256 * e];
    __syncthreads();

    float l[4], ex[4];
    float acc = 0.0f;
#pragma unroll
    for (int e = 0; e < 4; e++) {
        int j = t + 256 * e;
        l[e] = g_logits[base + j];
        ex[e] = __expf(l[e]);
        acc += ex[e] * (scm[j] - l[e]);
    }
    red[t] = acc; __syncthreads();
    for (int s = 128; s > 0; s >>= 1) { if (t < s) red[t] += red[t + s]; __syncthreads(); }
    const float rinv = g_rowinv[i];
    const float A = -red[0] * rinv * INVN;

#pragma unroll
    for (int e = 0; e < 4; e++) {
        int j = t + 256 * e;
        float a = sqrtf(-l[e]);
        float fv;
        if (a < 1e-3f) fv = -2.0f;
        else {
            float sh = 0.5f * (__expf(a) - __expf(-a));
            fv = -2.0f * a / sh;
        }
        float pv = ex[e] * rinv;
        float w = pv * (fmaf(scm[j] - l[e], INVN, A)) * fv;
        __nv_bfloat16 hi, lo; split2b(w, hi, lo);
        g_Wrow[0][base + j] = hi;
        g_Wrow[1][base + j] = lo;
    }
}

// ================= AdamW + reproject + emit p3 fp16 split =================
__global__ __launch_bounds__(256) void adam_kernel(float corr1, float corr2) {
    __shared__ float red[256];
    const int j = blockIdx.x;
    const int t = threadIdx.x;
    const size_t p3base = (size_t)j * K1;

    float ss = 0.0f;
#pragma unroll
    for (int e = 0; e < 2; e++) {
        int c = t + 256 * e;
        int d = c + 1;
        int idx = j * DP + d;
        float g = 0.0f;
#pragma unroll
        for (int z = 0; z < NSPLIT; z++)
            g += g_gpart[(size_t)z * NC * NDIM2 + (size_t)j * NDIM2 + c];
        float m = 0.9f * g_m[idx] + 0.1f * g;
        float v = 0.999f * g_v[idx] + 0.001f * (g * g);
        g_m[idx] = m; g_v[idx] = v;
        float mh = m * corr1;
        float vh = v * corr2;
        float xx = g_protos[idx] * 0.999f - 0.1f * mh / (sqrtf(vh) + EPS8);
        g_protos[idx] = xx;
        __half hi, lo; split2h(xx, hi, lo);
        g_p3[p3base + d] = hi;
        g_p3[p3base + SEC + d] = lo;
        g_p3[p3base + 2 * SEC + d] = hi;
        ss += xx * xx;
    }
    red[t] = ss; __syncthreads();
    for (int sft = 128; sft > 0; sft >>= 1) { if (t < sft) red[t] += red[t + sft]; __syncthreads(); }
    if (t == 0) {
        float tm = sqrtf(1.0f + red[0]);
        g_protos[j * DP] = tm;
        __half hi, lo; split2h(tm, hi, lo);
        g_p3[p3base] = hi;
        g_p3[p3base + SEC] = lo;
        g_p3[p3base + 2 * SEC] = hi;
    }
}

__global__ void pack_kernel(float* __restrict__ out) {
    int idx = blockIdx.x * blockDim.x + threadIdx.x;
    if (idx >= NC * DD) return;
    int i = idx / DD, d = idx % DD;
    out[idx] = g_protos[i * DP + d];
}

// ================= launch =================
extern "C" void kernel_launch(void* const* d_in, const int* in_sizes, int n_in,
                              void* d_out, int out_size) {
    const float* protos_in = (const float*)d_in[0];
    const float* query_in  = (const float*)d_in[1];
    (void)in_sizes; (void)n_in; (void)out_size;

    cudaFuncSetAttribute(mma_gemm<1>, cudaFuncAttributeMaxDynamicSharedMemorySize, SMEM_BYTES);
    cudaFuncSetAttribute(mma_gemm<2>, cudaFuncAttributeMaxDynamicSharedMemorySize, SMEM_BYTES);

    prep_q_kernel<<<(NQ * DP + 255) / 256, 256>>>(query_in);
    prep_q3_kernel<<<(NQ * K1 + 255) / 256, 256>>>();
    prep_qT2_kernel<<<(NDIM2 * NQ + 255) / 256, 256>>>();
    prep_p_kernel<<<(NC * DP + 255) / 256, 256>>>(protos_in);
    split_p_kernel<<<(NC * K1 + 255) / 256, 256>>>();

    for (int t = 1; t <= NITER; t++) {
        mma_gemm<1><<<dim3(NC / 128, NQ / 128), 256, SMEM_BYTES>>>();
        colpart_kernel<<<dim3(NC / 256, 32), 256>>>();
        rowdot_w_kernel<<<NQ, 256>>>();
        mma_gemm<2><<<dim3(NDIM2 / 128, NC / 128, NSPLIT), 256, SMEM_BYTES>>>();
        double c1 = 1.0 / (1.0 - pow(0.9,   (double)t));
        double c2 = 1.0 / (1.0 - pow(0.999, (double)t));
        adam_kernel<<<NC, 256>>>((float)c1, (float)c2);
    }
    pack_kernel<<<(NC * DD + 255) / 256, 256>>>((float*)d_out);
}

// round 13
// speedup vs baseline: 1.1072x; 1.0205x over previous
#include <cuda_runtime.h>
#include <cuda_bf16.h>
#include <cuda_fp16.h>
#include <math.h>
#include <stdint.h>

#define NQ 4096
#define NC 1024
#define DD 513
#define DP 528            // fp32 padded dim
#define SEC 528           // gemm1 section width
#define K1 1600           // 3 sections * 528 = 1584 -> pad to 1600 (25*64)
#define NDIM2 512         // gemm2 N (space coords 1..512)
#define KSEC 4096         // gemm2 per-section K
#define NSPLIT 9          // gemm2 slices: 3 section-pairs x 3 K-thirds
#define NITER 20
#define EPS8 1e-8f
#define INVN (1.0f/4096.0f)

__device__ __forceinline__ uint32_t smem_u32(const void* p) {
    uint32_t a;
    asm("{ .reg .u64 t; cvta.to.shared.u64 t, %1; cvt.u32.u64 %0, t; }" : "=r"(a) : "l"(p));
    return a;
}

// ================= persistent buffers =================
__device__ float g_qhat  [NQ * DP];
__device__ float g_protos[NC * DP];
__device__ float g_logits[NQ * NC];
__device__ float g_rowpart[16][NQ];      // per-(colblock,wn) partial exp-sums
__device__ float g_rowinv[NQ];
__device__ float g_cm    [NC];
__device__ float g_colpart[32 * NC];
__device__ float g_m     [NC * DP];
__device__ float g_v     [NC * DP];
__device__ __half g_q3 [(size_t)NQ * K1];                 // [qh|qh|ql] fp16
__device__ __half g_p3 [(size_t)NC * K1];                 // [ph|pl|ph] fp16
__device__ __nv_bfloat16 g_qT2[2][(size_t)NDIM2 * KSEC];  // [qh^T], [ql^T] bf16
__device__ __nv_bfloat16 g_Wrow[2][(size_t)NQ * NC];      // Wh, Wl row-major [i][j]
__device__ float g_gpart[NSPLIT * (size_t)NC * NDIM2];

__device__ __forceinline__ void split2b(float v, __nv_bfloat16& hi, __nv_bfloat16& lo) {
    hi = __float2bfloat16(v);
    lo = __float2bfloat16(v - __bfloat162float(hi));
}
__device__ __forceinline__ void split2h(float v, __half& hi, __half& lo) {
    hi = __float2half(v);
    lo = __float2half(v - __half2float(hi));
}

// ================= prep =================
__global__ void prep_q_kernel(const float* __restrict__ q) {
    int idx = blockIdx.x * blockDim.x + threadIdx.x;
    if (idx >= NQ * DP) return;
    int i = idx / DP, d = idx % DP;
    float v = 0.0f;
    if (d < DD) { v = q[i * DD + d]; if (d > 0) v = -v; }
    g_qhat[idx] = v;
}
__global__ void prep_q3_kernel() {
    int idx = blockIdx.x * blockDim.x + threadIdx.x;
    if (idx >= NQ * K1) return;
    int i = idx / K1, d = idx % K1;
    __half out = __float2half(0.0f);
    if (d < 3 * SEC) {
        int sec = d / SEC, dd = d % SEC;
        float v = g_qhat[i * DP + dd];
        __half hi, lo; split2h(v, hi, lo);
        out = (sec < 2) ? hi : lo;
    }
    g_q3[(size_t)i * K1 + d] = out;
}
__global__ void prep_qT2_kernel() {
    int idx = blockIdx.x * blockDim.x + threadIdx.x;
    if (idx >= NDIM2 * NQ) return;
    int r = idx / NQ, i = idx % NQ;
    float v = g_qhat[i * DP + r + 1];
    __nv_bfloat16 hi, lo; split2b(v, hi, lo);
    g_qT2[0][(size_t)r * KSEC + i] = hi;
    g_qT2[1][(size_t)r * KSEC + i] = lo;
}
__global__ void prep_p_kernel(const float* __restrict__ p) {
    int idx = blockIdx.x * blockDim.x + threadIdx.x;
    if (idx >= NC * DP) return;
    int i = idx / DP, d = idx % DP;
    float v = 0.0f;
    if (d < DD) v = p[i * DD + d];
    g_protos[idx] = v;
    g_m[idx] = 0.0f;
    g_v[idx] = 0.0f;
}
__global__ void split_p_kernel() {
    int idx = blockIdx.x * blockDim.x + threadIdx.x;
    if (idx >= NC * K1) return;
    int j = idx / K1, d = idx % K1;
    __half out = __float2half(0.0f);
    if (d < 3 * SEC) {
        int sec = d / SEC, dd = d % SEC;
        float v = g_protos[j * DP + dd];
        __half hi, lo; split2h(v, hi, lo);
        out = (sec == 1) ? lo : hi;
    }
    g_p3[(size_t)j * K1 + d] = out;
}

// ================= mma.sync GEMM (3-stage cp.async pipeline) =================
#define SMEM_BYTES 98304

__device__ __forceinline__ void ld_x4(uint32_t* r, uint32_t addr) {
    asm volatile("ldmatrix.sync.aligned.m8n8.x4.shared.b16 {%0,%1,%2,%3}, [%4];"
        : "=r"(r[0]), "=r"(r[1]), "=r"(r[2]), "=r"(r[3]) : "r"(addr));
}
__device__ __forceinline__ void ld_x4_trans(uint32_t* r, uint32_t addr) {
    asm volatile("ldmatrix.sync.aligned.m8n8.x4.trans.shared.b16 {%0,%1,%2,%3}, [%4];"
        : "=r"(r[0]), "=r"(r[1]), "=r"(r[2]), "=r"(r[3]) : "r"(addr));
}
__device__ __forceinline__ void mma_bf16(float* d, const uint32_t* a, const uint32_t* b) {
    asm volatile("mma.sync.aligned.m16n8k16.row.col.f32.bf16.bf16.f32 "
        "{%0,%1,%2,%3}, {%4,%5,%6,%7}, {%8,%9}, {%0,%1,%2,%3};"
        : "+f"(d[0]), "+f"(d[1]), "+f"(d[2]), "+f"(d[3])
        : "r"(a[0]), "r"(a[1]), "r"(a[2]), "r"(a[3]), "r"(b[0]), "r"(b[1]));
}
__device__ __forceinline__ void mma_fp16(float* d, const uint32_t* a, const uint32_t* b) {
    asm volatile("mma.sync.aligned.m16n8k16.row.col.f32.f16.f16.f32 "
        "{%0,%1,%2,%3}, {%4,%5,%6,%7}, {%8,%9}, {%0,%1,%2,%3};"
        : "+f"(d[0]), "+f"(d[1]), "+f"(d[2]), "+f"(d[3])
        : "r"(a[0]), "r"(a[1]), "r"(a[2]), "r"(a[3]), "r"(b[0]), "r"(b[1]));
}

// MODE1 stage: A,B both K-major 128 rows x 128B
__device__ __forceinline__ void load_stage1(uint32_t sA, const char* Ab, const char* Bb,
                                            size_t kbytes, size_t gk, int tid) {
    uint32_t sB = sA + 16384;
#pragma unroll
    for (int t = 0; t < 4; t++) {
        int idx = tid + 256 * t;
        int r = idx >> 3, c = idx & 7;
        uint32_t sw = (uint32_t)(r * 128 + ((c ^ (r & 7)) << 4));
        const char* g = Ab + (size_t)r * kbytes + gk + c * 16;
        asm volatile("cp.async.cg.shared.global [%0], [%1], 16;" :: "r"(sA + sw), "l"(g));
    }
#pragma unroll
    for (int t = 0; t < 4; t++) {
        int idx = tid + 256 * t;
        int r = idx >> 3, c = idx & 7;
        uint32_t sw = (uint32_t)(r * 128 + ((c ^ (r & 7)) << 4));
        const char* g = Bb + (size_t)r * kbytes + gk + c * 16;
        asm volatile("cp.async.cg.shared.global [%0], [%1], 16;" :: "r"(sB + sw), "l"(g));
    }
    asm volatile("cp.async.commit_group;" ::: "memory");
}

// MODE2 stage: A = W row-major tile (64 k-rows x 256B), B = qT2 K-major (128 rows x 128B)
__device__ __forceinline__ void load_stage2(uint32_t sA, const char* AbW, const char* Bb,
                                            int krow0, int tid) {
    uint32_t sB = sA + 16384;
#pragma unroll
    for (int t = 0; t < 4; t++) {
        int idx = tid + 256 * t;
        int row = idx >> 4, col = idx & 15;
        uint32_t scol = (uint32_t)(col ^ (row & 7));
        const char* g = AbW + (size_t)(krow0 + row) * (NC * 2) + col * 16;
        asm volatile("cp.async.cg.shared.global [%0], [%1], 16;"
            :: "r"(sA + row * 256 + scol * 16), "l"(g));
    }
#pragma unroll
    for (int t = 0; t < 4; t++) {
        int idx = tid + 256 * t;
        int r = idx >> 3, c = idx & 7;
        uint32_t sw = (uint32_t)(r * 128 + ((c ^ (r & 7)) << 4));
        const char* g = Bb + (size_t)r * (KSEC * 2) + (size_t)krow0 * 2 + c * 16;
        asm volatile("cp.async.cg.shared.global [%0], [%1], 16;" :: "r"(sB + sw), "l"(g));
    }
    asm volatile("cp.async.commit_group;" ::: "memory");
}

template <int MODE>
__global__ __launch_bounds__(256, 2) void mma_gemm() {
    extern __shared__ char smem[];
    const uint32_t sb = smem_u32(smem);
    const int tid = threadIdx.x;
    const int warp = tid >> 5, lane = tid & 31;
    const int wm = warp & 3, wn = warp >> 2;

    const int m0 = blockIdx.y * 128;
    const int n0 = blockIdx.x * 128;
    const char* Abase;
    const char* Bbase;
    int nch, krowbase = 0;
    if (MODE == 1) {
        Abase = (const char*)g_q3 + (size_t)m0 * K1 * 2;
        Bbase = (const char*)g_p3 + (size_t)n0 * K1 * 2;
        nch = K1 / 64;
    } else {
        int z = blockIdx.z;
        int s = z / 3, h = z % 3;
        int ai = (s == 2) ? 1 : 0;
        int bi = (s == 1) ? 1 : 0;
        Abase = (const char*)&g_Wrow[ai][0] + (size_t)m0 * 2;      // + krow*NC*2
        Bbase = (const char*)&g_qT2[bi][0] + (size_t)n0 * KSEC * 2;
        nch = (h < 2) ? 22 : 20;
        krowbase = h * 22 * 64;
    }

    if (MODE == 1) {
        load_stage1(sb, Abase, Bbase, K1 * 2, 0, tid);
        load_stage1(sb + 32768, Abase, Bbase, K1 * 2, 128, tid);
    } else {
        load_stage2(sb, Abase, Bbase, krowbase, tid);
        load_stage2(sb + 32768, Abase, Bbase, krowbase + 64, tid);
    }
    asm volatile("cp.async.wait_group 1;" ::: "memory");
    __syncthreads();

    float acc[2][8][4];
#pragma unroll
    for (int mt = 0; mt < 2; mt++)
#pragma unroll
        for (int nt = 0; nt < 8; nt++)
#pragma unroll
            for (int e = 0; e < 4; e++) acc[mt][nt][e] = 0.0f;

    for (int ch = 0; ch < nch; ch++) {
        const uint32_t sA = sb + (uint32_t)(ch % 3) * 32768;
        const uint32_t sB = sA + 16384;

#pragma unroll
        for (int kk = 0; kk < 4; kk++) {
            uint32_t a[2][4], b[8][2];
#pragma unroll
            for (int mt = 0; mt < 2; mt++) {
                if (MODE == 1) {
                    int r = wm * 32 + mt * 16 + (lane & 15);
                    int c = ((lane >> 4) + 2 * kk) ^ (r & 7);
                    ld_x4(a[mt], sA + r * 128 + c * 16);
                } else {
                    int krow = 16 * kk + (lane & 7) + ((lane >> 4) << 3);
                    int mcol = wm * 4 + mt * 2 + ((lane >> 3) & 1);
                    int scol = mcol ^ (krow & 7);
                    ld_x4_trans(a[mt], sA + krow * 256 + scol * 16);
                }
            }
#pragma unroll
            for (int np = 0; np < 4; np++) {
                int r = wn * 64 + np * 16 + (lane & 7) + ((lane >> 4) << 3);
                int c = (((lane >> 3) & 1) + 2 * kk) ^ (r & 7);
                uint32_t tmp[4];
                ld_x4(tmp, sB + r * 128 + c * 16);
                b[2 * np][0] = tmp[0]; b[2 * np][1] = tmp[1];
                b[2 * np + 1][0] = tmp[2]; b[2 * np + 1][1] = tmp[3];
            }
#pragma unroll
            for (int mt = 0; mt < 2; mt++)
#pragma unroll
                for (int nt = 0; nt < 8; nt++) {
                    if (MODE == 1) mma_fp16(acc[mt][nt], a[mt], b[nt]);
                    else           mma_bf16(acc[mt][nt], a[mt], b[nt]);
                }
        }

        if (ch + 2 < nch) {
            if (MODE == 1)
                load_stage1(sb + (uint32_t)((ch + 2) % 3) * 32768, Abase, Bbase,
                            K1 * 2, (size_t)(ch + 2) * 128, tid);
            else
                load_stage2(sb + (uint32_t)((ch + 2) % 3) * 32768, Abase, Bbase,
                            krowbase + (ch + 2) * 64, tid);
            asm volatile("cp.async.wait_group 1;" ::: "memory");
        } else {
            asm volatile("cp.async.wait_group 0;" ::: "memory");
        }
        __syncthreads();
    }

    // ---------------- epilogue ----------------
    if (MODE == 1) {
        const float CL = 1.0f + 1e-7f;
        float rowE[2][2] = {{0.0f, 0.0f}, {0.0f, 0.0f}};
#pragma unroll
        for (int mt = 0; mt < 2; mt++) {
#pragma unroll
            for (int nt = 0; nt < 8; nt++) {
                int col = n0 + wn * 64 + nt * 8 + (lane & 3) * 2;
#pragma unroll
                for (int h = 0; h < 2; h++) {
                    int row = m0 + wm * 32 + mt * 16 + (lane >> 2) + 8 * h;
                    float v0 = acc[mt][nt][2 * h + 0];
                    float v1 = acc[mt][nt][2 * h + 1];
                    float2 lg;
                    {
                        float z = fmaxf(v0, CL);
                        float w = fmaf(z, z, -1.0f);
                        float aa = __logf(fmaf(w, rsqrtf(w), z));
                        lg.x = -aa * aa;
                    }
                    {
                        float z = fmaxf(v1, CL);
                        float w = fmaf(z, z, -1.0f);
                        float aa = __logf(fmaf(w, rsqrtf(w), z));
                        lg.y = -aa * aa;
                    }
                    *(float2*)&g_logits[(size_t)row * NC + col] = lg;
                    rowE[mt][h] += __expf(lg.x) + __expf(lg.y);
                }
            }
        }
#pragma unroll
        for (int mt = 0; mt < 2; mt++)
#pragma unroll
            for (int h = 0; h < 2; h++) {
                float r = rowE[mt][h];
                r += __shfl_xor_sync(0xFFFFFFFFu, r, 1);
                r += __shfl_xor_sync(0xFFFFFFFFu, r, 2);
                if ((lane & 3) == 0) {
                    int row = m0 + wm * 32 + mt * 16 + (lane >> 2) + 8 * h;
                    g_rowpart[blockIdx.x * 2 + wn][row] = r;
                }
            }
    } else {
#pragma unroll
        for (int mt = 0; mt < 2; mt++) {
#pragma unroll
            for (int nt = 0; nt < 8; nt++) {
                int col = n0 + wn * 64 + nt * 8 + (lane & 3) * 2;
#pragma unroll
                for (int h = 0; h < 2; h++) {
                    int row = m0 + wm * 32 + mt * 16 + (lane >> 2) + 8 * h;
                    float* out = g_gpart + (size_t)blockIdx.z * NC * NDIM2;
                    float2 gv;
                    gv.x = acc[mt][nt][2 * h + 0];
                    gv.y = acc[mt][nt][2 * h + 1];
                    *(float2*)&out[(size_t)row * NDIM2 + col] = gv;
                }
            }
        }
    }
}

// ================= elementwise chain =================
// colpart (rowinv fused): col partial sums of P = exp(l)*rowinv over 128-row blocks
__global__ __launch_bounds__(256) void colpart_kernel() {
    __shared__ float srinv[128];
    const int t = threadIdx.x;
    const int i0 = blockIdx.y * 128;
    if (t < 128) {
        float s = 0.0f;
#pragma unroll
        for (int r = 0; r < 16; r++) s += g_rowpart[r][i0 + t];
        float inv = 1.0f / s;
        srinv[t] = inv;
        if (blockIdx.x == 0) g_rowinv[i0 + t] = inv;
    }
    __syncthreads();
    const int j = blockIdx.x * 256 + t;
    float s = 0.0f;
#pragma unroll 8
    for (int i = 0; i < 128; i++)
        s += __expf(g_logits[(size_t)(i0 + i) * NC + j]) * srinv[i];
    g_colpart[blockIdx.y * NC + j] = s;
}

__global__ __launch_bounds__(256) void colreduce_kernel() {
    const int j = blockIdx.x * 256 + threadIdx.x;
    float s = 0.0f;
#pragma unroll
    for (int r = 0; r < 32; r++) s += g_colpart[r * NC + j];
    float pm = s * INVN;
    g_cm[j] = __logf(pm + EPS8) + pm / (pm + EPS8);
}

// fused rowdot + W: A_i then W_ij = P*((cm_j-l)*invN + A_i)*factor, row-major bf16 split
// float2 logit loads + paired bf16x2 W stores.
__global__ __launch_bounds__(256) void rowdot_w_kernel() {
    __shared__ float scm[NC];
    __shared__ float red[256];
    const int i = blockIdx.x;
    const int t = threadIdx.x;
    const size_t base = (size_t)i * NC;
#pragma unroll
    for (int e = 0; e < 4; e++) scm[t + 256 * e] = g_cm[t + 256 * e];
    __syncthreads();

    float l[4], ex[4];
    float acc = 0.0f;
#pragma unroll
    for (int e = 0; e < 2; e++) {
        int j = 2 * t + 512 * e;
        float2 lv = *(const float2*)&g_logits[base + j];
        l[2 * e] = lv.x; l[2 * e + 1] = lv.y;
        ex[2 * e] = __expf(lv.x);
        ex[2 * e + 1] = __expf(lv.y);
        acc += ex[2 * e] * (scm[j] - lv.x);
        acc += ex[2 * e + 1] * (scm[j + 1] - lv.y);
    }
    red[t] = acc; __syncthreads();
    for (int s = 128; s > 0; s >>= 1) { if (t < s) red[t] += red[t + s]; __syncthreads(); }
    const float rinv = g_rowinv[i];
    const float A = -red[0] * rinv * INVN;

#pragma unroll
    for (int e = 0; e < 2; e++) {
        int j = 2 * t + 512 * e;
        float wv[2];
#pragma unroll
        for (int u = 0; u < 2; u++) {
            float lv = l[2 * e + u];
            float a = sqrtf(-lv);
            float fv;
            if (a < 1e-3f) fv = -2.0f;
            else {
                float sh = 0.5f * (__expf(a) - __expf(-a));
                fv = -2.0f * a / sh;
            }
            float pv = ex[2 * e + u] * rinv;
            wv[u] = pv * (fmaf(scm[j + u] - lv, INVN, A)) * fv;
        }
        __nv_bfloat16 h0, l0, h1, l1;
        split2b(wv[0], h0, l0); split2b(wv[1], h1, l1);
        __nv_bfloat162 hh; hh.x = h0; hh.y = h1;
        __nv_bfloat162 ll; ll.x = l0; ll.y = l1;
        *(__nv_bfloat162*)&g_Wrow[0][base + j] = hh;
        *(__nv_bfloat162*)&g_Wrow[1][base + j] = ll;
    }
}

// ================= AdamW + reproject + emit p3 fp16 split =================
__global__ __launch_bounds__(256) void adam_kernel(float corr1, float corr2) {
    __shared__ float red[256];
    const int j = blockIdx.x;
    const int t = threadIdx.x;
    const size_t p3base = (size_t)j * K1;

    float ss = 0.0f;
#pragma unroll
    for (int e = 0; e < 2; e++) {
        int c = t + 256 * e;
        int d = c + 1;
        int idx = j * DP + d;
        float g = 0.0f;
#pragma unroll
        for (int z = 0; z < NSPLIT; z++)
            g += g_gpart[(size_t)z * NC * NDIM2 + (size_t)j * NDIM2 + c];
        float m = 0.9f * g_m[idx] + 0.1f * g;
        float v = 0.999f * g_v[idx] + 0.001f * (g * g);
        g_m[idx] = m; g_v[idx] = v;
        float mh = m * corr1;
        float vh = v * corr2;
        float xx = g_protos[idx] * 0.999f - 0.1f * mh / (sqrtf(vh) + EPS8);
        g_protos[idx] = xx;
        __half hi, lo; split2h(xx, hi, lo);
        g_p3[p3base + d] = hi;
        g_p3[p3base + SEC + d] = lo;
        g_p3[p3base + 2 * SEC + d] = hi;
        ss += xx * xx;
    }
    red[t] = ss; __syncthreads();
    for (int sft = 128; sft > 0; sft >>= 1) { if (t < sft) red[t] += red[t + sft]; __syncthreads(); }
    if (t == 0) {
        float tm = sqrtf(1.0f + red[0]);
        g_protos[j * DP] = tm;
        __half hi, lo; split2h(tm, hi, lo);
        g_p3[p3base] = hi;
        g_p3[p3base + SEC] = lo;
        g_p3[p3base + 2 * SEC] = hi;
    }
}

__global__ void pack_kernel(float* __restrict__ out) {
    int idx = blockIdx.x * blockDim.x + threadIdx.x;
    if (idx >= NC * DD) return;
    int i = idx / DD, d = idx % DD;
    out[idx] = g_protos[i * DP + d];
}

// ================= launch =================
extern "C" void kernel_launch(void* const* d_in, const int* in_sizes, int n_in,
                              void* d_out, int out_size) {
    const float* protos_in = (const float*)d_in[0];
    const float* query_in  = (const float*)d_in[1];
    (void)in_sizes; (void)n_in; (void)out_size;

    cudaFuncSetAttribute(mma_gemm<1>, cudaFuncAttributeMaxDynamicSharedMemorySize, SMEM_BYTES);
    cudaFuncSetAttribute(mma_gemm<2>, cudaFuncAttributeMaxDynamicSharedMemorySize, SMEM_BYTES);

    prep_q_kernel<<<(NQ * DP + 255) / 256, 256>>>(query_in);
    prep_q3_kernel<<<(NQ * K1 + 255) / 256, 256>>>();
    prep_qT2_kernel<<<(NDIM2 * NQ + 255) / 256, 256>>>();
    prep_p_kernel<<<(NC * DP + 255) / 256, 256>>>(protos_in);
    split_p_kernel<<<(NC * K1 + 255) / 256, 256>>>();

    for (int t = 1; t <= NITER; t++) {
        mma_gemm<1><<<dim3(NC / 128, NQ / 128), 256, SMEM_BYTES>>>();
        colpart_kernel<<<dim3(NC / 256, 32), 256>>>();
        colreduce_kernel<<<NC / 256, 256>>>();
        rowdot_w_kernel<<<NQ, 256>>>();
        mma_gemm<2><<<dim3(NDIM2 / 128, NC / 128, NSPLIT), 256, SMEM_BYTES>>>();
        double c1 = 1.0 / (1.0 - pow(0.9,   (double)t));
        double c2 = 1.0 / (1.0 - pow(0.999, (double)t));
        adam_kernel<<<NC, 256>>>((float)c1, (float)c2);
    }
    pack_kernel<<<(NC * DD + 255) / 256, 256>>>((float*)d_out);
}

// round 14
// speedup vs baseline: 1.1235x; 1.0147x over previous
#include <cuda_runtime.h>
#include <cuda_bf16.h>
#include <cuda_fp16.h>
#include <math.h>
#include <stdint.h>

#define NQ 4096
#define NC 1024
#define DD 513
#define DP 528            // fp32 padded dim
#define SEC 528           // gemm1 section width
#define K1 1600           // 3 sections * 528 = 1584 -> pad to 1600 (25*64)
#define NDIM2 512         // gemm2 N (space coords 1..512)
#define KSEC 4096         // gemm2 per-section K
#define NSPLIT 9          // gemm2 slices: 3 section-pairs x 3 K-thirds
#define NITER 20
#define EPS8 1e-8f
#define INVN (1.0f/4096.0f)

__device__ __forceinline__ uint32_t smem_u32(const void* p) {
    uint32_t a;
    asm("{ .reg .u64 t; cvta.to.shared.u64 t, %1; cvt.u32.u64 %0, t; }" : "=r"(a) : "l"(p));
    return a;
}

// ================= persistent buffers =================
__device__ float g_protos[NC * DP];
__device__ float g_logits[NQ * NC];
__device__ float g_rowpart[16][NQ];      // per-(colblock,wn) partial exp-sums
__device__ float g_rowinv[NQ];
__device__ float g_cm    [NC];
__device__ float g_colpart[32 * NC];
__device__ float g_m     [NC * DP];
__device__ float g_v     [NC * DP];
__device__ __half g_q3 [(size_t)NQ * K1];                 // [qh|qh|ql] fp16
__device__ __half g_p3 [(size_t)NC * K1];                 // [ph|pl|ph] fp16
__device__ __nv_bfloat16 g_qT2[2][(size_t)NDIM2 * KSEC];  // [qh^T], [ql^T] bf16
__device__ __nv_bfloat16 g_Wrow[2][(size_t)NQ * NC];      // Wh, Wl row-major [i][j]
__device__ float g_gpart[NSPLIT * (size_t)NC * NDIM2];

__device__ __forceinline__ void split2b(float v, __nv_bfloat16& hi, __nv_bfloat16& lo) {
    hi = __float2bfloat16(v);
    lo = __float2bfloat16(v - __bfloat162float(hi));
}
__device__ __forceinline__ void split2h(float v, __half& hi, __half& lo) {
    hi = __float2half(v);
    lo = __float2half(v - __half2float(hi));
}

// ================= prep (3 independent kernels) =================
// q3 directly from raw query input: [qh|qh|ql] + zero pad
__global__ void prep_q3_direct(const float* __restrict__ q) {
    int idx = blockIdx.x * blockDim.x + threadIdx.x;
    if (idx >= NQ * DP) return;
    int i = idx / DP, d = idx % DP;
    float v = 0.0f;
    if (d < DD) { v = q[i * DD + d]; if (d > 0) v = -v; }
    __half hi, lo; split2h(v, hi, lo);
    size_t base = (size_t)i * K1;
    g_q3[base + d] = hi;
    g_q3[base + SEC + d] = hi;
    g_q3[base + 2 * SEC + d] = lo;
    if (d < K1 - 3 * SEC)                       // 16 pad columns
        g_q3[base + 3 * SEC + d] = __float2half(0.0f);
}
// qT2 directly from raw query input (space coords, negated)
__global__ void prep_qT2_direct(const float* __restrict__ q) {
    int idx = blockIdx.x * blockDim.x + threadIdx.x;
    if (idx >= NDIM2 * NQ) return;
    int r = idx / NQ, i = idx % NQ;
    float v = -q[i * DD + r + 1];
    __nv_bfloat16 hi, lo; split2b(v, hi, lo);
    g_qT2[0][(size_t)r * KSEC + i] = hi;
    g_qT2[1][(size_t)r * KSEC + i] = lo;
}
// protos + m/v init + initial p3 split, one pass
__global__ void prep_p_all(const float* __restrict__ p) {
    int idx = blockIdx.x * blockDim.x + threadIdx.x;
    if (idx >= NC * DP) return;
    int i = idx / DP, d = idx % DP;
    float v = 0.0f;
    if (d < DD) v = p[i * DD + d];
    g_protos[idx] = v;
    g_m[idx] = 0.0f;
    g_v[idx] = 0.0f;
    __half hi, lo; split2h(v, hi, lo);
    size_t base = (size_t)i * K1;
    g_p3[base + d] = hi;
    g_p3[base + SEC + d] = lo;
    g_p3[base + 2 * SEC + d] = hi;
    if (d < K1 - 3 * SEC)
        g_p3[base + 3 * SEC + d] = __float2half(0.0f);
}

// ================= mma.sync GEMM (3-stage cp.async pipeline) =================
#define SMEM_BYTES 98304

__device__ __forceinline__ void ld_x4(uint32_t* r, uint32_t addr) {
    asm volatile("ldmatrix.sync.aligned.m8n8.x4.shared.b16 {%0,%1,%2,%3}, [%4];"
        : "=r"(r[0]), "=r"(r[1]), "=r"(r[2]), "=r"(r[3]) : "r"(addr));
}
__device__ __forceinline__ void ld_x4_trans(uint32_t* r, uint32_t addr) {
    asm volatile("ldmatrix.sync.aligned.m8n8.x4.trans.shared.b16 {%0,%1,%2,%3}, [%4];"
        : "=r"(r[0]), "=r"(r[1]), "=r"(r[2]), "=r"(r[3]) : "r"(addr));
}
__device__ __forceinline__ void mma_bf16(float* d, const uint32_t* a, const uint32_t* b) {
    asm volatile("mma.sync.aligned.m16n8k16.row.col.f32.bf16.bf16.f32 "
        "{%0,%1,%2,%3}, {%4,%5,%6,%7}, {%8,%9}, {%0,%1,%2,%3};"
        : "+f"(d[0]), "+f"(d[1]), "+f"(d[2]), "+f"(d[3])
        : "r"(a[0]), "r"(a[1]), "r"(a[2]), "r"(a[3]), "r"(b[0]), "r"(b[1]));
}
__device__ __forceinline__ void mma_fp16(float* d, const uint32_t* a, const uint32_t* b) {
    asm volatile("mma.sync.aligned.m16n8k16.row.col.f32.f16.f16.f32 "
        "{%0,%1,%2,%3}, {%4,%5,%6,%7}, {%8,%9}, {%0,%1,%2,%3};"
        : "+f"(d[0]), "+f"(d[1]), "+f"(d[2]), "+f"(d[3])
        : "r"(a[0]), "r"(a[1]), "r"(a[2]), "r"(a[3]), "r"(b[0]), "r"(b[1]));
}

// MODE1 stage: A,B both K-major 128 rows x 128B
__device__ __forceinline__ void load_stage1(uint32_t sA, const char* Ab, const char* Bb,
                                            size_t kbytes, size_t gk, int tid) {
    uint32_t sB = sA + 16384;
#pragma unroll
    for (int t = 0; t < 4; t++) {
        int idx = tid + 256 * t;
        int r = idx >> 3, c = idx & 7;
        uint32_t sw = (uint32_t)(r * 128 + ((c ^ (r & 7)) << 4));
        const char* g = Ab + (size_t)r * kbytes + gk + c * 16;
        asm volatile("cp.async.cg.shared.global [%0], [%1], 16;" :: "r"(sA + sw), "l"(g));
    }
#pragma unroll
    for (int t = 0; t < 4; t++) {
        int idx = tid + 256 * t;
        int r = idx >> 3, c = idx & 7;
        uint32_t sw = (uint32_t)(r * 128 + ((c ^ (r & 7)) << 4));
        const char* g = Bb + (size_t)r * kbytes + gk + c * 16;
        asm volatile("cp.async.cg.shared.global [%0], [%1], 16;" :: "r"(sB + sw), "l"(g));
    }
    asm volatile("cp.async.commit_group;" ::: "memory");
}

// MODE2 stage: A = W row-major tile (64 k-rows x 256B), B = qT2 K-major (128 rows x 128B)
__device__ __forceinline__ void load_stage2(uint32_t sA, const char* AbW, const char* Bb,
                                            int krow0, int tid) {
    uint32_t sB = sA + 16384;
#pragma unroll
    for (int t = 0; t < 4; t++) {
        int idx = tid + 256 * t;
        int row = idx >> 4, col = idx & 15;
        uint32_t scol = (uint32_t)(col ^ (row & 7));
        const char* g = AbW + (size_t)(krow0 + row) * (NC * 2) + col * 16;
        asm volatile("cp.async.cg.shared.global [%0], [%1], 16;"
            :: "r"(sA + row * 256 + scol * 16), "l"(g));
    }
#pragma unroll
    for (int t = 0; t < 4; t++) {
        int idx = tid + 256 * t;
        int r = idx >> 3, c = idx & 7;
        uint32_t sw = (uint32_t)(r * 128 + ((c ^ (r & 7)) << 4));
        const char* g = Bb + (size_t)r * (KSEC * 2) + (size_t)krow0 * 2 + c * 16;
        asm volatile("cp.async.cg.shared.global [%0], [%1], 16;" :: "r"(sB + sw), "l"(g));
    }
    asm volatile("cp.async.commit_group;" ::: "memory");
}

template <int MODE>
__global__ __launch_bounds__(256, 2) void mma_gemm() {
    extern __shared__ char smem[];
    const uint32_t sb = smem_u32(smem);
    const int tid = threadIdx.x;
    const int warp = tid >> 5, lane = tid & 31;
    const int wm = warp & 3, wn = warp >> 2;

    const int m0 = blockIdx.y * 128;
    const int n0 = blockIdx.x * 128;
    const char* Abase;
    const char* Bbase;
    int nch, krowbase = 0;
    if (MODE == 1) {
        Abase = (const char*)g_q3 + (size_t)m0 * K1 * 2;
        Bbase = (const char*)g_p3 + (size_t)n0 * K1 * 2;
        nch = K1 / 64;
    } else {
        int z = blockIdx.z;
        int s = z / 3, h = z % 3;
        int ai = (s == 2) ? 1 : 0;
        int bi = (s == 1) ? 1 : 0;
        Abase = (const char*)&g_Wrow[ai][0] + (size_t)m0 * 2;      // + krow*NC*2
        Bbase = (const char*)&g_qT2[bi][0] + (size_t)n0 * KSEC * 2;
        nch = (h < 2) ? 22 : 20;
        krowbase = h * 22 * 64;
    }

    if (MODE == 1) {
        load_stage1(sb, Abase, Bbase, K1 * 2, 0, tid);
        load_stage1(sb + 32768, Abase, Bbase, K1 * 2, 128, tid);
    } else {
        load_stage2(sb, Abase, Bbase, krowbase, tid);
        load_stage2(sb + 32768, Abase, Bbase, krowbase + 64, tid);
    }
    asm volatile("cp.async.wait_group 1;" ::: "memory");
    __syncthreads();

    float acc[2][8][4];
#pragma unroll
    for (int mt = 0; mt < 2; mt++)
#pragma unroll
        for (int nt = 0; nt < 8; nt++)
#pragma unroll
            for (int e = 0; e < 4; e++) acc[mt][nt][e] = 0.0f;

    for (int ch = 0; ch < nch; ch++) {
        const uint32_t sA = sb + (uint32_t)(ch % 3) * 32768;
        const uint32_t sB = sA + 16384;

#pragma unroll
        for (int kk = 0; kk < 4; kk++) {
            uint32_t a[2][4], b[8][2];
#pragma unroll
            for (int mt = 0; mt < 2; mt++) {
                if (MODE == 1) {
                    int r = wm * 32 + mt * 16 + (lane & 15);
                    int c = ((lane >> 4) + 2 * kk) ^ (r & 7);
                    ld_x4(a[mt], sA + r * 128 + c * 16);
                } else {
                    int krow = 16 * kk + (lane & 7) + ((lane >> 4) << 3);
                    int mcol = wm * 4 + mt * 2 + ((lane >> 3) & 1);
                    int scol = mcol ^ (krow & 7);
                    ld_x4_trans(a[mt], sA + krow * 256 + scol * 16);
                }
            }
#pragma unroll
            for (int np = 0; np < 4; np++) {
                int r = wn * 64 + np * 16 + (lane & 7) + ((lane >> 4) << 3);
                int c = (((lane >> 3) & 1) + 2 * kk) ^ (r & 7);
                uint32_t tmp[4];
                ld_x4(tmp, sB + r * 128 + c * 16);
                b[2 * np][0] = tmp[0]; b[2 * np][1] = tmp[1];
                b[2 * np + 1][0] = tmp[2]; b[2 * np + 1][1] = tmp[3];
            }
#pragma unroll
            for (int mt = 0; mt < 2; mt++)
#pragma unroll
                for (int nt = 0; nt < 8; nt++) {
                    if (MODE == 1) mma_fp16(acc[mt][nt], a[mt], b[nt]);
                    else           mma_bf16(acc[mt][nt], a[mt], b[nt]);
                }
        }

        if (ch + 2 < nch) {
            if (MODE == 1)
                load_stage1(sb + (uint32_t)((ch + 2) % 3) * 32768, Abase, Bbase,
                            K1 * 2, (size_t)(ch + 2) * 128, tid);
            else
                load_stage2(sb + (uint32_t)((ch + 2) % 3) * 32768, Abase, Bbase,
                            krowbase + (ch + 2) * 64, tid);
            asm volatile("cp.async.wait_group 1;" ::: "memory");
        } else {
            asm volatile("cp.async.wait_group 0;" ::: "memory");
        }
        __syncthreads();
    }

    // ---------------- epilogue ----------------
    if (MODE == 1) {
        const float CL = 1.0f + 1e-7f;
        float rowE[2][2] = {{0.0f, 0.0f}, {0.0f, 0.0f}};
#pragma unroll
        for (int mt = 0; mt < 2; mt++) {
#pragma unroll
            for (int nt = 0; nt < 8; nt++) {
                int col = n0 + wn * 64 + nt * 8 + (lane & 3) * 2;
#pragma unroll
                for (int h = 0; h < 2; h++) {
                    int row = m0 + wm * 32 + mt * 16 + (lane >> 2) + 8 * h;
                    float v0 = acc[mt][nt][2 * h + 0];
                    float v1 = acc[mt][nt][2 * h + 1];
                    float2 lg;
                    {
                        float z = fmaxf(v0, CL);
                        float w = fmaf(z, z, -1.0f);
                        float aa = __logf(fmaf(w, rsqrtf(w), z));
                        lg.x = -aa * aa;
                    }
                    {
                        float z = fmaxf(v1, CL);
                        float w = fmaf(z, z, -1.0f);
                        float aa = __logf(fmaf(w, rsqrtf(w), z));
                        lg.y = -aa * aa;
                    }
                    *(float2*)&g_logits[(size_t)row * NC + col] = lg;
                    rowE[mt][h] += __expf(lg.x) + __expf(lg.y);
                }
            }
        }
#pragma unroll
        for (int mt = 0; mt < 2; mt++)
#pragma unroll
            for (int h = 0; h < 2; h++) {
                float r = rowE[mt][h];
                r += __shfl_xor_sync(0xFFFFFFFFu, r, 1);
                r += __shfl_xor_sync(0xFFFFFFFFu, r, 2);
                if ((lane & 3) == 0) {
                    int row = m0 + wm * 32 + mt * 16 + (lane >> 2) + 8 * h;
                    g_rowpart[blockIdx.x * 2 + wn][row] = r;
                }
            }
    } else {
#pragma unroll
        for (int mt = 0; mt < 2; mt++) {
#pragma unroll
            for (int nt = 0; nt < 8; nt++) {
                int col = n0 + wn * 64 + nt * 8 + (lane & 3) * 2;
#pragma unroll
                for (int h = 0; h < 2; h++) {
                    int row = m0 + wm * 32 + mt * 16 + (lane >> 2) + 8 * h;
                    float* out = g_gpart + (size_t)blockIdx.z * NC * NDIM2;
                    float2 gv;
                    gv.x = acc[mt][nt][2 * h + 0];
                    gv.y = acc[mt][nt][2 * h + 1];
                    *(float2*)&out[(size_t)row * NDIM2 + col] = gv;
                }
            }
        }
    }
}

// ================= elementwise chain =================
__global__ __launch_bounds__(256) void colpart_kernel() {
    __shared__ float srinv[128];
    const int t = threadIdx.x;
    const int i0 = blockIdx.y * 128;
    if (t < 128) {
        float s = 0.0f;
#pragma unroll
        for (int r = 0; r < 16; r++) s += g_rowpart[r][i0 + t];
        float inv = 1.0f / s;
        srinv[t] = inv;
        if (blockIdx.x == 0) g_rowinv[i0 + t] = inv;
    }
    __syncthreads();
    const int j = blockIdx.x * 256 + t;
    float s = 0.0f;
#pragma unroll 8
    for (int i = 0; i < 128; i++)
        s += __expf(g_logits[(size_t)(i0 + i) * NC + j]) * srinv[i];
    g_colpart[blockIdx.y * NC + j] = s;
}

__global__ __launch_bounds__(256) void colreduce_kernel() {
    const int j = blockIdx.x * 256 + threadIdx.x;
    float s = 0.0f;
#pragma unroll
    for (int r = 0; r < 32; r++) s += g_colpart[r * NC + j];
    float pm = s * INVN;
    g_cm[j] = __logf(pm + EPS8) + pm / (pm + EPS8);
}

// fused rowdot + W (float2 loads, bf16x2 paired stores)
__global__ __launch_bounds__(256) void rowdot_w_kernel() {
    __shared__ float scm[NC];
    __shared__ float red[256];
    const int i = blockIdx.x;
    const int t = threadIdx.x;
    const size_t base = (size_t)i * NC;
#pragma unroll
    for (int e = 0; e < 4; e++) scm[t + 256 * e] = g_cm[t + 256 * e];
    __syncthreads();

    float l[4], ex[4];
    float acc = 0.0f;
#pragma unroll
    for (int e = 0; e < 2; e++) {
        int j = 2 * t + 512 * e;
        float2 lv = *(const float2*)&g_logits[base + j];
        l[2 * e] = lv.x; l[2 * e + 1] = lv.y;
        ex[2 * e] = __expf(lv.x);
        ex[2 * e + 1] = __expf(lv.y);
        acc += ex[2 * e] * (scm[j] - lv.x);
        acc += ex[2 * e + 1] * (scm[j + 1] - lv.y);
    }
    red[t] = acc; __syncthreads();
    for (int s = 128; s > 0; s >>= 1) { if (t < s) red[t] += red[t + s]; __syncthreads(); }
    const float rinv = g_rowinv[i];
    const float A = -red[0] * rinv * INVN;

#pragma unroll
    for (int e = 0; e < 2; e++) {
        int j = 2 * t + 512 * e;
        float wv[2];
#pragma unroll
        for (int u = 0; u < 2; u++) {
            float lv = l[2 * e + u];
            float a = sqrtf(-lv);
            float fv;
            if (a < 1e-3f) fv = -2.0f;
            else {
                float sh = 0.5f * (__expf(a) - __expf(-a));
                fv = -2.0f * a / sh;
            }
            float pv = ex[2 * e + u] * rinv;
            wv[u] = pv * (fmaf(scm[j + u] - lv, INVN, A)) * fv;
        }
        __nv_bfloat16 h0, l0, h1, l1;
        split2b(wv[0], h0, l0); split2b(wv[1], h1, l1);
        __nv_bfloat162 hh; hh.x = h0; hh.y = h1;
        __nv_bfloat162 ll; ll.x = l0; ll.y = l1;
        *(__nv_bfloat162*)&g_Wrow[0][base + j] = hh;
        *(__nv_bfloat162*)&g_Wrow[1][base + j] = ll;
    }
}

// ================= AdamW + reproject + emit p3 fp16 split =================
__global__ __launch_bounds__(256) void adam_kernel(float corr1, float corr2) {
    __shared__ float red[256];
    const int j = blockIdx.x;
    const int t = threadIdx.x;
    const size_t p3base = (size_t)j * K1;

    float ss = 0.0f;
#pragma unroll
    for (int e = 0; e < 2; e++) {
        int c = t + 256 * e;
        int d = c + 1;
        int idx = j * DP + d;
        float g = 0.0f;
#pragma unroll
        for (int z = 0; z < NSPLIT; z++)
            g += g_gpart[(size_t)z * NC * NDIM2 + (size_t)j * NDIM2 + c];
        float m = 0.9f * g_m[idx] + 0.1f * g;
        float v = 0.999f * g_v[idx] + 0.001f * (g * g);
        g_m[idx] = m; g_v[idx] = v;
        float mh = m * corr1;
        float vh = v * corr2;
        float xx = g_protos[idx] * 0.999f - 0.1f * mh / (sqrtf(vh) + EPS8);
        g_protos[idx] = xx;
        __half hi, lo; split2h(xx, hi, lo);
        g_p3[p3base + d] = hi;
        g_p3[p3base + SEC + d] = lo;
        g_p3[p3base + 2 * SEC + d] = hi;
        ss += xx * xx;
    }
    red[t] = ss; __syncthreads();
    for (int sft = 128; sft > 0; sft >>= 1) { if (t < sft) red[t] += red[t + sft]; __syncthreads(); }
    if (t == 0) {
        float tm = sqrtf(1.0f + red[0]);
        g_protos[j * DP] = tm;
        __half hi, lo; split2h(tm, hi, lo);
        g_p3[p3base] = hi;
        g_p3[p3base + SEC] = lo;
        g_p3[p3base + 2 * SEC] = hi;
    }
}

__global__ void pack_kernel(float* __restrict__ out) {
    int idx = blockIdx.x * blockDim.x + threadIdx.x;
    if (idx >= NC * DD) return;
    int i = idx / DD, d = idx % DD;
    out[idx] = g_protos[i * DP + d];
}

// ================= launch =================
extern "C" void kernel_launch(void* const* d_in, const int* in_sizes, int n_in,
                              void* d_out, int out_size) {
    const float* protos_in = (const float*)d_in[0];
    const float* query_in  = (const float*)d_in[1];
    (void)in_sizes; (void)n_in; (void)out_size;

    cudaFuncSetAttribute(mma_gemm<1>, cudaFuncAttributeMaxDynamicSharedMemorySize, SMEM_BYTES);
    cudaFuncSetAttribute(mma_gemm<2>, cudaFuncAttributeMaxDynamicSharedMemorySize, SMEM_BYTES);

    prep_q3_direct<<<(NQ * DP + 255) / 256, 256>>>(query_in);
    prep_qT2_direct<<<(NDIM2 * NQ + 255) / 256, 256>>>(query_in);
    prep_p_all<<<(NC * DP + 255) / 256, 256>>>(protos_in);

    for (int t = 1; t <= NITER; t++) {
        mma_gemm<1><<<dim3(NC / 128, NQ / 128), 256, SMEM_BYTES>>>();
        colpart_kernel<<<dim3(NC / 256, 32), 256>>>();
        colreduce_kernel<<<NC / 256, 256>>>();
        rowdot_w_kernel<<<NQ, 256>>>();
        mma_gemm<2><<<dim3(NDIM2 / 128, NC / 128, NSPLIT), 256, SMEM_BYTES>>>();
        double c1 = 1.0 / (1.0 - pow(0.9,   (double)t));
        double c2 = 1.0 / (1.0 - pow(0.999, (double)t));
        adam_kernel<<<NC, 256>>>((float)c1, (float)c2);
    }
    pack_kernel<<<(NC * DD + 255) / 256, 256>>>((float*)d_out);
}